// round 13
// baseline (speedup 1.0000x reference)
#include <cuda_runtime.h>
#include <cuda_bf16.h>
#include <cstdint>

#define NT 288              // 8 compute warps + 1 producer warp
#define NCW 256             // compute threads
#define DD 256
#define NEG_BIG (-1e30f)

// ---- static scratch: converted s2 (swizzle baked into 512B rows) + part2 ----
#define MAXROWS (32 * 1024)
__device__ __align__(128) char  g_s2hi[(size_t)MAXROWS * 512];
__device__ __align__(128) char  g_s2lo[(size_t)MAXROWS * 512];
__device__ __align__(128) float g_part2[MAXROWS];

// ---- smem byte offsets (from 128B-aligned base) ----
#define QHI_OFF 0           // [128][256] bf16 hi, 512B/row, swizzled
#define QLO_OFF 65536       // [128][256] bf16 lo
#define KBUF_OFF 131072     // 3 x { KHI 16KB, KLO 16KB }
#define KBUF_STRIDE 32768
#define P2_OFF  229376      // 3 x 128B bias slices
#define P1_OFF  229760      // 128 f32
#define MBAR_OFF 230272     // full[3] then free[3], 8B each
#define SMEM_USED 230320
#define SMEM_BYTES (SMEM_USED + 128)

__device__ __forceinline__ uint32_t smem_u32(const void* p) {
    uint32_t a;
    asm("{ .reg .u64 t; cvta.to.shared.u64 t, %1; cvt.u32.u64 %0, t; }"
        : "=r"(a) : "l"(p));
    return a;
}

#define CP_ASYNC16(dst, src) \
    asm volatile("cp.async.cg.shared.global [%0], [%1], 16;" \
        :: "r"(dst), "l"(src) : "memory")
#define CP_WAIT0()  asm volatile("cp.async.wait_group 0;" ::: "memory")
#define CP_COMMIT() asm volatile("cp.async.commit_group;" ::: "memory")

#define MBARRIER_INIT(mbar, count) \
    asm volatile("mbarrier.init.shared.b64 [%0], %1;" \
        :: "r"((uint32_t)(mbar)), "r"((uint32_t)(count)) : "memory")
#define MBARRIER_ARRIVE(mbar) \
    asm volatile("mbarrier.arrive.shared.b64 _, [%0];" \
        :: "r"((uint32_t)(mbar)) : "memory")
#define CPASYNC_MBAR_ARRIVE(mbar) \
    asm volatile("cp.async.mbarrier.arrive.noinc.shared.b64 [%0];" \
        :: "r"((uint32_t)(mbar)) : "memory")

#define MBARRIER_WAIT_PARITY(mbar, parity) do {                               \
    uint32_t _m = (uint32_t)(mbar);                                           \
    uint32_t _p = (uint32_t)(parity);                                         \
    asm volatile(                                                             \
        "{\n\t.reg .pred P1;\n\t"                                             \
        "WAIT_LOOP_%=:\n\t"                                                   \
        "mbarrier.try_wait.parity.acquire.cta.shared::cta.b64 P1, [%0], %1, 0x989680;\n\t" \
        "@P1 bra.uni WAIT_DONE_%=;\n\t"                                       \
        "bra.uni WAIT_LOOP_%=;\n\t"                                           \
        "WAIT_DONE_%=:\n\t}"                                                  \
        :: "r"(_m), "r"(_p) : "memory");                                      \
} while (0)

__device__ __forceinline__ void ldsm_x4(uint32_t& a0, uint32_t& a1, uint32_t& a2,
                                        uint32_t& a3, uint32_t addr) {
    asm volatile("ldmatrix.sync.aligned.m8n8.x4.shared.b16 {%0,%1,%2,%3}, [%4];"
                 : "=r"(a0), "=r"(a1), "=r"(a2), "=r"(a3) : "r"(addr));
}
__device__ __forceinline__ void ldsm_x4t(uint32_t& a0, uint32_t& a1, uint32_t& a2,
                                         uint32_t& a3, uint32_t addr) {
    asm volatile("ldmatrix.sync.aligned.m8n8.x4.trans.shared.b16 {%0,%1,%2,%3}, [%4];"
                 : "=r"(a0), "=r"(a1), "=r"(a2), "=r"(a3) : "r"(addr));
}
__device__ __forceinline__ void mma16816(float* c, uint32_t a0, uint32_t a1,
                                         uint32_t a2, uint32_t a3,
                                         uint32_t b0, uint32_t b1) {
    asm volatile(
        "mma.sync.aligned.m16n8k16.row.col.f32.bf16.bf16.f32 "
        "{%0,%1,%2,%3}, {%4,%5,%6,%7}, {%8,%9}, {%0,%1,%2,%3};"
        : "+f"(c[0]), "+f"(c[1]), "+f"(c[2]), "+f"(c[3])
        : "r"(a0), "r"(a1), "r"(a2), "r"(a3), "r"(b0), "r"(b1));
}

__device__ __forceinline__ uint32_t swz(int row, int chunk, int rowbytes) {
    int c = (chunk & ~7) | ((chunk & 7) ^ (row & 7));
    return (uint32_t)(row * rowbytes + c * 16);
}

__device__ __forceinline__ uint32_t pk2(__nv_bfloat16 a, __nv_bfloat16 b) {
    __nv_bfloat162 t; t.x = a; t.y = b;
    return *reinterpret_cast<uint32_t*>(&t);
}

__device__ __forceinline__ void split2(float a, float b, uint32_t& hi, uint32_t& lo) {
    __nv_bfloat16 ha = __float2bfloat16(a), hb = __float2bfloat16(b);
    float ra = a - __bfloat162float(ha), rb = b - __bfloat162float(hb);
    hi = pk2(ha, hb);
    lo = pk2(__float2bfloat16(ra), __float2bfloat16(rb));
}

// =============== prepass: s2 -> bf16 hi/lo (swizzled rows) + part2 ===============
__global__ void __launch_bounds__(256, 2)
prep_s2(const float* __restrict__ s2, const float* __restrict__ w,
        const int* __restrict__ l2, int t2, int total_rows)
{
    const int row = blockIdx.x * 32 + (threadIdx.x >> 3);
    const int h   = threadIdx.x & 7;
    if (row >= total_rows) return;
    if ((row % t2) >= l2[row / t2]) return;

    const float4* sr  = (const float4*)(s2 + (size_t)row * DD);
    const float4* w2v = (const float4*)(w + DD);
    char* hrow = g_s2hi + (size_t)row * 512;
    char* lrow = g_s2lo + (size_t)row * 512;

    float acc = 0.f;
    #pragma unroll
    for (int p = 0; p < 8; p++) {
        int c4 = h + 8 * p;
        float4 v = sr[c4];
        float4 a2 = w2v[c4];
        acc += v.x * a2.x + v.y * a2.y + v.z * a2.z + v.w * a2.w;
        uint32_t hA, lA, hB, lB;
        split2(v.x, v.y, hA, lA); split2(v.z, v.w, hB, lB);
        int chunk = c4 >> 1;
        uint32_t off = (uint32_t)(((chunk & ~7) | ((chunk & 7) ^ (row & 7))) * 16
                                  + (c4 & 1) * 8);
        *(uint2*)(hrow + off) = make_uint2(hA, hB);
        *(uint2*)(lrow + off) = make_uint2(lA, lB);
    }
    acc += __shfl_xor_sync(0xffffffffu, acc, 1);
    acc += __shfl_xor_sync(0xffffffffu, acc, 2);
    acc += __shfl_xor_sync(0xffffffffu, acc, 4);
    if (h == 0) g_part2[row] = acc;
}

// ============================== main kernel ==============================
__global__ void __launch_bounds__(NT, 1)
bidaf_fa2(const float* __restrict__ s1, const float* __restrict__ s2,
          const float* __restrict__ w, const int* __restrict__ l1,
          const int* __restrict__ l2, float* __restrict__ out, int t1)
{
    extern __shared__ char sm_raw[];
    char* smc = (char*)(((uintptr_t)sm_raw + 127) & ~(uintptr_t)127);

    const int b   = blockIdx.y;
    const int m0  = blockIdx.x * 128;
    const int tid = threadIdx.x;
    const int L1v = l1[b], L2v = l2[b];
    float* outTile = out + ((size_t)b * t1 + m0) * DD;

    if (m0 >= L1v || L2v == 0) {
        float4 z = make_float4(0.f, 0.f, 0.f, 0.f);
        for (int i = tid; i < 128 * DD / 4; i += NT) ((float4*)outTile)[i] = z;
        return;
    }

    const uint32_t smem = smem_u32(smc);
    const int lane = tid & 31;
    const int wid  = tid >> 5;
    const int bbase = b * 1024;
    const int nchunks = (L2v + 31) >> 5;

    const uint32_t mb_full0 = smem + MBAR_OFF;
    const uint32_t mb_free0 = smem + MBAR_OFF + 24;

    if (tid == 0) {
        #pragma unroll
        for (int i = 0; i < 3; i++) {
            MBARRIER_INIT(mb_full0 + i * 8, 32);    // producer warp arrivals
            MBARRIER_INIT(mb_free0 + i * 8, NCW);   // compute thread arrivals
        }
    }

    // ---- producer issues fill of chunk 0 (buffer 0) before the sync ----
    if (wid == 8) {
        const char* srcH = g_s2hi + (size_t)(bbase + lane) * 512;
        const char* srcL = g_s2lo + (size_t)(bbase + lane) * 512;
        uint32_t dstH = smem + KBUF_OFF + (uint32_t)lane * 512;
        uint32_t dstL = dstH + 16384;
        #pragma unroll
        for (int i = 0; i < 32; i++) {
            CP_ASYNC16(dstH + i * 16, srcH + i * 16);
            CP_ASYNC16(dstL + i * 16, srcL + i * 16);
        }
        if (lane < 8)
            CP_ASYNC16(smem + P2_OFF + lane * 16,
                       (const char*)(g_part2 + bbase) + lane * 16);
    }

    // ---- prologue (compute threads): Q = s1*w3 -> bf16 hi/lo smem; part1 ----
    if (tid < NCW) {
        const float* s1b = s1 + ((size_t)b * t1 + m0) * DD;
        const float4* w1v = (const float4*)w;
        const float4* w3v = (const float4*)(w + 2 * DD);
        const int row = tid >> 1, h = tid & 1;
        const float4* qr = (const float4*)(s1b + row * DD);
        float acc = 0.f;
        #pragma unroll
        for (int i = 0; i < 32; i++) {
            int c4 = 2 * i + h;
            float4 v = qr[c4];
            float4 a1 = w1v[c4];
            acc += v.x * a1.x + v.y * a1.y + v.z * a1.z + v.w * a1.w;
            float4 m3 = w3v[c4];
            float q0 = v.x * m3.x, q1 = v.y * m3.y, q2 = v.z * m3.z, q3 = v.w * m3.w;
            uint32_t hA, lA, hB, lB;
            split2(q0, q1, hA, lA); split2(q2, q3, hB, lB);
            uint32_t off = swz(row, i, 512) + h * 8;
            *(uint2*)(smc + QHI_OFF + off) = make_uint2(hA, hB);
            *(uint2*)(smc + QLO_OFF + off) = make_uint2(lA, lB);
        }
        acc += __shfl_xor_sync(0xffffffffu, acc, 1);
        if (h == 0) ((float*)(smc + P1_OFF))[row] = acc;
    }
    __syncthreads();   // Q/P1 visible; mbarriers initialized

    if (wid == 8) {
        // ================= producer warp =================
        CPASYNC_MBAR_ARRIVE(mb_full0);   // covers fill 0
        int bf = 1, fu = 0;
        for (int j = 1; j < nchunks; j++) {
            if (fu >= 1)
                MBARRIER_WAIT_PARITY(mb_free0 + bf * 8, (fu - 1) & 1);
            const int r0 = bbase + j * 32 + lane;
            const char* srcH = g_s2hi + (size_t)r0 * 512;
            const char* srcL = g_s2lo + (size_t)r0 * 512;
            uint32_t dstH = smem + KBUF_OFF + (uint32_t)bf * KBUF_STRIDE
                            + (uint32_t)lane * 512;
            uint32_t dstL = dstH + 16384;
            #pragma unroll
            for (int i = 0; i < 32; i++) {
                CP_ASYNC16(dstH + i * 16, srcH + i * 16);
                CP_ASYNC16(dstL + i * 16, srcL + i * 16);
            }
            if (lane < 8)
                CP_ASYNC16(smem + P2_OFF + bf * 128 + lane * 16,
                           (const char*)(g_part2 + bbase + j * 32) + lane * 16);
            CPASYNC_MBAR_ARRIVE(mb_full0 + bf * 8);
            if (++bf == 3) { bf = 0; fu++; }
        }
        CP_COMMIT();
        CP_WAIT0();      // drain before exit
        return;
    }

    // ================= compute warps =================
    const int lam = lane & 3;
    const int r0l = wid * 16 + (lane >> 2);
    const int arow = wid * 16 + (lane & 15);
    const int brow = (lane & 7) + ((lane >> 4) & 1) * 8;
    const float p1a = ((const float*)(smc + P1_OFF))[r0l];
    const float p1b = ((const float*)(smc + P1_OFF))[r0l + 8];

    float O[32][4];
    #pragma unroll
    for (int j = 0; j < 32; j++)
        #pragma unroll
        for (int e = 0; e < 4; e++) O[j][e] = 0.f;
    float mrow0 = -INFINITY, mrow1 = -INFINITY, lrow0 = 0.f, lrow1 = 0.f;

    int bf = 0, fu = 0;
    for (int i = 0; i < nchunks; i++) {
        const uint32_t kh = smem + KBUF_OFF + (uint32_t)bf * KBUF_STRIDE;
        const uint32_t kl = kh + 16384;
        const float* p2f = (const float*)(smc + P2_OFF + bf * 128);
        const int c0 = i * 32;

        MBARRIER_WAIT_PARITY(mb_full0 + bf * 8, fu & 1);

        // ---- score: 16 rows x 32 cols; term-grouped (4 indep chains) ----
        float c[4][4];
        #pragma unroll
        for (int j = 0; j < 4; j++)
            #pragma unroll
            for (int e = 0; e < 4; e++) c[j][e] = 0.f;

        #pragma unroll 4
        for (int k = 0; k < 16; k++) {
            uint32_t aoff = swz(arow, 2 * k + (lane >> 4), 512);
            uint32_t ah0, ah1, ah2, ah3, al0, al1, al2, al3;
            ldsm_x4(ah0, ah1, ah2, ah3, smem + QHI_OFF + aoff);
            ldsm_x4(al0, al1, al2, al3, smem + QLO_OFF + aoff);
            uint32_t boff0 = swz(brow, 2 * k + ((lane >> 3) & 1), 512);
            uint32_t boff1 = swz(brow + 16, 2 * k + ((lane >> 3) & 1), 512);
            uint32_t b00, b01, b02, b03, b10, b11, b12, b13;
            uint32_t l00, l01, l02, l03, l10, l11, l12, l13;
            ldsm_x4(b00, b01, b02, b03, kh + boff0);
            ldsm_x4(b10, b11, b12, b13, kh + boff1);
            ldsm_x4(l00, l01, l02, l03, kl + boff0);
            ldsm_x4(l10, l11, l12, l13, kl + boff1);
            mma16816(c[0], ah0, ah1, ah2, ah3, b00, b01);
            mma16816(c[1], ah0, ah1, ah2, ah3, b02, b03);
            mma16816(c[2], ah0, ah1, ah2, ah3, b10, b11);
            mma16816(c[3], ah0, ah1, ah2, ah3, b12, b13);
            mma16816(c[0], ah0, ah1, ah2, ah3, l00, l01);
            mma16816(c[1], ah0, ah1, ah2, ah3, l02, l03);
            mma16816(c[2], ah0, ah1, ah2, ah3, l10, l11);
            mma16816(c[3], ah0, ah1, ah2, ah3, l12, l13);
            mma16816(c[0], al0, al1, al2, al3, b00, b01);
            mma16816(c[1], al0, al1, al2, al3, b02, b03);
            mma16816(c[2], al0, al1, al2, al3, b10, b11);
            mma16816(c[3], al0, al1, al2, al3, b12, b13);
        }

        // ---- warp-local online softmax ----
        float mx0 = -INFINITY, mx1 = -INFINITY;
        #pragma unroll
        for (int j = 0; j < 4; j++) {
            #pragma unroll
            for (int e = 0; e < 2; e++) {
                int col = j * 8 + 2 * lam + e;
                bool valid = (c0 + col) < L2v;
                float bias = p2f[col];
                float s0 = c[j][e] + p1a + bias;
                float s1v = c[j][e + 2] + p1b + bias;
                s0 = valid ? s0 : NEG_BIG;
                s1v = valid ? s1v : NEG_BIG;
                c[j][e] = s0; c[j][e + 2] = s1v;
                mx0 = fmaxf(mx0, s0); mx1 = fmaxf(mx1, s1v);
            }
        }
        mx0 = fmaxf(mx0, __shfl_xor_sync(0xffffffffu, mx0, 1));
        mx0 = fmaxf(mx0, __shfl_xor_sync(0xffffffffu, mx0, 2));
        mx1 = fmaxf(mx1, __shfl_xor_sync(0xffffffffu, mx1, 1));
        mx1 = fmaxf(mx1, __shfl_xor_sync(0xffffffffu, mx1, 2));

        const float mnew0 = fmaxf(mrow0, mx0), mnew1 = fmaxf(mrow1, mx1);
        const float alpha0 = __expf(mrow0 - mnew0), alpha1 = __expf(mrow1 - mnew1);
        mrow0 = mnew0; mrow1 = mnew1;

        float sum0 = 0.f, sum1 = 0.f;
        #pragma unroll
        for (int j = 0; j < 4; j++) {
            c[j][0] = __expf(c[j][0] - mnew0);
            c[j][1] = __expf(c[j][1] - mnew0);
            c[j][2] = __expf(c[j][2] - mnew1);
            c[j][3] = __expf(c[j][3] - mnew1);
            sum0 += c[j][0] + c[j][1];
            sum1 += c[j][2] + c[j][3];
        }
        sum0 += __shfl_xor_sync(0xffffffffu, sum0, 1);
        sum0 += __shfl_xor_sync(0xffffffffu, sum0, 2);
        sum1 += __shfl_xor_sync(0xffffffffu, sum1, 1);
        sum1 += __shfl_xor_sync(0xffffffffu, sum1, 2);
        lrow0 = lrow0 * alpha0 + sum0;
        lrow1 = lrow1 * alpha1 + sum1;

        // ---- pack P c-frags into PV a-frags ----
        uint32_t pah[8], pal[8];
        #pragma unroll
        for (int kk = 0; kk < 2; kk++) {
            const int J = 2 * kk;
            split2(c[J][0],     c[J][1],     pah[4 * kk + 0], pal[4 * kk + 0]);
            split2(c[J][2],     c[J][3],     pah[4 * kk + 1], pal[4 * kk + 1]);
            split2(c[J + 1][0], c[J + 1][1], pah[4 * kk + 2], pal[4 * kk + 2]);
            split2(c[J + 1][2], c[J + 1][3], pah[4 * kk + 3], pal[4 * kk + 3]);
        }

        // ---- rescale O ----
        #pragma unroll
        for (int j = 0; j < 32; j++) {
            O[j][0] *= alpha0; O[j][1] *= alpha0;
            O[j][2] *= alpha1; O[j][3] *= alpha1;
        }

        // ---- PV: paired d-blocks, term-grouped (4 indep chains) ----
        #pragma unroll
        for (int kk = 0; kk < 2; kk++) {
            const int vrow = kk * 16 + (lane & 15);
            const uint32_t a0 = pah[4 * kk], a1 = pah[4 * kk + 1],
                           a2 = pah[4 * kk + 2], a3 = pah[4 * kk + 3];
            const uint32_t b0 = pal[4 * kk], b1 = pal[4 * kk + 1],
                           b2 = pal[4 * kk + 2], b3 = pal[4 * kk + 3];
            #pragma unroll
            for (int dp = 0; dp < 8; dp++) {
                uint32_t boff0 = swz(vrow, 4 * dp + (lane >> 4), 512);
                uint32_t boff1 = swz(vrow, 4 * dp + 2 + (lane >> 4), 512);
                uint32_t vh0, vh1, vh2, vh3, wh0, wh1, wh2, wh3;
                uint32_t vl0, vl1, vl2, vl3, wl0, wl1, wl2, wl3;
                ldsm_x4t(vh0, vh1, vh2, vh3, kh + boff0);
                ldsm_x4t(wh0, wh1, wh2, wh3, kh + boff1);
                ldsm_x4t(vl0, vl1, vl2, vl3, kl + boff0);
                ldsm_x4t(wl0, wl1, wl2, wl3, kl + boff1);
                float* O0 = O[4 * dp], *O1 = O[4 * dp + 1];
                float* O2 = O[4 * dp + 2], *O3 = O[4 * dp + 3];
                mma16816(O0, a0, a1, a2, a3, vh0, vh1);
                mma16816(O1, a0, a1, a2, a3, vh2, vh3);
                mma16816(O2, a0, a1, a2, a3, wh0, wh1);
                mma16816(O3, a0, a1, a2, a3, wh2, wh3);
                mma16816(O0, a0, a1, a2, a3, vl0, vl1);
                mma16816(O1, a0, a1, a2, a3, vl2, vl3);
                mma16816(O2, a0, a1, a2, a3, wl0, wl1);
                mma16816(O3, a0, a1, a2, a3, wl2, wl3);
                mma16816(O0, b0, b1, b2, b3, vh0, vh1);
                mma16816(O1, b0, b1, b2, b3, vh2, vh3);
                mma16816(O2, b0, b1, b2, b3, wh0, wh1);
                mma16816(O3, b0, b1, b2, b3, wh2, wh3);
            }
        }

        MBARRIER_ARRIVE(mb_free0 + bf * 8);   // done reading buffer bf
        if (++bf == 3) { bf = 0; fu++; }
    }

    // ---------------- epilogue ----------------
    const int gr0 = m0 + r0l, gr1 = gr0 + 8;
    const float inv0 = (gr0 < L1v) ? (1.f / lrow0) : 0.f;
    const float inv1 = (gr1 < L1v) ? (1.f / lrow1) : 0.f;
    float* orow0 = outTile + r0l * DD + 2 * lam;
    float* orow1 = orow0 + 8 * DD;
    #pragma unroll
    for (int j = 0; j < 32; j++) {
        float2 v0; v0.x = O[j][0] * inv0; v0.y = O[j][1] * inv0;
        float2 v1; v1.x = O[j][2] * inv1; v1.y = O[j][3] * inv1;
        *(float2*)(orow0 + j * 8) = v0;
        *(float2*)(orow1 + j * 8) = v1;
    }
}

extern "C" void kernel_launch(void* const* d_in, const int* in_sizes, int n_in,
                              void* d_out, int out_size)
{
    const float* s1 = (const float*)d_in[0];
    const float* s2 = (const float*)d_in[1];
    const float* w  = (const float*)d_in[2];
    const int*   l1 = (const int*)d_in[3];
    const int*   l2 = (const int*)d_in[4];
    float* out = (float*)d_out;

    const int B  = in_sizes[3];
    const int D  = in_sizes[2] / 3;
    const int t1 = in_sizes[0] / (B * D);
    const int t2 = in_sizes[1] / (B * D);
    const int total_rows = B * t2;

    prep_s2<<<(total_rows + 31) / 32, 256>>>(s2, w, l2, t2, total_rows);

    cudaFuncSetAttribute(bidaf_fa2, cudaFuncAttributeMaxDynamicSharedMemorySize,
                         SMEM_BYTES);
    dim3 grid(t1 / 128, B);
    bidaf_fa2<<<grid, NT, SMEM_BYTES>>>(s1, s2, w, l1, l2, out, t1);
}

// round 14
// speedup vs baseline: 1.5312x; 1.5312x over previous
#include <cuda_runtime.h>
#include <cuda_bf16.h>
#include <cstdint>

#define NT 256
#define DD 256
#define NEG_BIG (-1e30f)
#define MHEAD 8.0f

// ---- static scratch: converted s2 (swizzle baked into 512B rows) + part2 ----
#define MAXROWS (32 * 1024)
__device__ __align__(128) char  g_s2hi[(size_t)MAXROWS * 512];
__device__ __align__(128) char  g_s2lo[(size_t)MAXROWS * 512];
__device__ __align__(128) float g_part2[MAXROWS];

// ---- smem byte offsets (from 128B-aligned base) ----
#define QHI_OFF 0           // [128][256] bf16 hi, 512B/row, swizzled
#define QLO_OFF 65536       // [128][256] bf16 lo
#define KBUF_OFF 131072     // 2 x { KHI 16KB, KLO 16KB }
#define KBUF_STRIDE 32768
#define P2_OFF  196608      // 2 x 128B bias slices
#define SMEM_USED 196864
#define SMEM_BYTES (SMEM_USED + 128)

__device__ __forceinline__ uint32_t smem_u32(const void* p) {
    uint32_t a;
    asm("{ .reg .u64 t; cvta.to.shared.u64 t, %1; cvt.u32.u64 %0, t; }"
        : "=r"(a) : "l"(p));
    return a;
}

#define CP_ASYNC16(dst, src) \
    asm volatile("cp.async.cg.shared.global [%0], [%1], 16;" \
        :: "r"(dst), "l"(src) : "memory")
#define CP_COMMIT() asm volatile("cp.async.commit_group;" ::: "memory")
#define CP_WAIT0()  asm volatile("cp.async.wait_group 0;" ::: "memory")

__device__ __forceinline__ void ldsm_x4(uint32_t& a0, uint32_t& a1, uint32_t& a2,
                                        uint32_t& a3, uint32_t addr) {
    asm volatile("ldmatrix.sync.aligned.m8n8.x4.shared.b16 {%0,%1,%2,%3}, [%4];"
                 : "=r"(a0), "=r"(a1), "=r"(a2), "=r"(a3) : "r"(addr));
}
__device__ __forceinline__ void ldsm_x4t(uint32_t& a0, uint32_t& a1, uint32_t& a2,
                                         uint32_t& a3, uint32_t addr) {
    asm volatile("ldmatrix.sync.aligned.m8n8.x4.trans.shared.b16 {%0,%1,%2,%3}, [%4];"
                 : "=r"(a0), "=r"(a1), "=r"(a2), "=r"(a3) : "r"(addr));
}
__device__ __forceinline__ void mma16816(float* c, uint32_t a0, uint32_t a1,
                                         uint32_t a2, uint32_t a3,
                                         uint32_t b0, uint32_t b1) {
    asm volatile(
        "mma.sync.aligned.m16n8k16.row.col.f32.bf16.bf16.f32 "
        "{%0,%1,%2,%3}, {%4,%5,%6,%7}, {%8,%9}, {%0,%1,%2,%3};"
        : "+f"(c[0]), "+f"(c[1]), "+f"(c[2]), "+f"(c[3])
        : "r"(a0), "r"(a1), "r"(a2), "r"(a3), "r"(b0), "r"(b1));
}

// swizzled chunk address: 16B chunks, XOR low-3 chunk bits with row&7
__device__ __forceinline__ uint32_t swz(int row, int chunk, int rowbytes) {
    int c = (chunk & ~7) | ((chunk & 7) ^ (row & 7));
    return (uint32_t)(row * rowbytes + c * 16);
}

__device__ __forceinline__ uint32_t pk2(__nv_bfloat16 a, __nv_bfloat16 b) {
    __nv_bfloat162 t; t.x = a; t.y = b;
    return *reinterpret_cast<uint32_t*>(&t);
}

__device__ __forceinline__ void split2(float a, float b, uint32_t& hi, uint32_t& lo) {
    __nv_bfloat16 ha = __float2bfloat16(a), hb = __float2bfloat16(b);
    float ra = a - __bfloat162float(ha), rb = b - __bfloat162float(hb);
    hi = pk2(ha, hb);
    lo = pk2(__float2bfloat16(ra), __float2bfloat16(rb));
}

// =============== prepass: s2 -> bf16 hi/lo (swizzled rows) + part2 ===============
__global__ void __launch_bounds__(256, 2)
prep_s2(const float* __restrict__ s2, const float* __restrict__ w,
        const int* __restrict__ l2, int t2, int total_rows)
{
    const int row = blockIdx.x * 32 + (threadIdx.x >> 3);
    const int h   = threadIdx.x & 7;
    if (row >= total_rows) return;
    if ((row % t2) >= l2[row / t2]) return;     // masked rows never read

    const float4* sr  = (const float4*)(s2 + (size_t)row * DD);
    const float4* w2v = (const float4*)(w + DD);
    char* hrow = g_s2hi + (size_t)row * 512;
    char* lrow = g_s2lo + (size_t)row * 512;

    float acc = 0.f;
    #pragma unroll
    for (int p = 0; p < 8; p++) {
        int c4 = h + 8 * p;
        float4 v = sr[c4];
        float4 a2 = w2v[c4];
        acc += v.x * a2.x + v.y * a2.y + v.z * a2.z + v.w * a2.w;
        uint32_t hA, lA, hB, lB;
        split2(v.x, v.y, hA, lA); split2(v.z, v.w, hB, lB);
        int chunk = c4 >> 1;
        uint32_t off = (uint32_t)(((chunk & ~7) | ((chunk & 7) ^ (row & 7))) * 16
                                  + (c4 & 1) * 8);
        *(uint2*)(hrow + off) = make_uint2(hA, hB);
        *(uint2*)(lrow + off) = make_uint2(lA, lB);
    }
    acc += __shfl_xor_sync(0xffffffffu, acc, 1);
    acc += __shfl_xor_sync(0xffffffffu, acc, 2);
    acc += __shfl_xor_sync(0xffffffffu, acc, 4);
    if (h == 0) g_part2[row] = acc;
}

// ============================== main kernel ==============================
__global__ void __launch_bounds__(NT, 1)
bidaf_fa2(const float* __restrict__ s1, const float* __restrict__ s2,
          const float* __restrict__ w, const int* __restrict__ l1,
          const int* __restrict__ l2, float* __restrict__ out, int t1)
{
    extern __shared__ char sm_raw[];
    char* smc = (char*)(((uintptr_t)sm_raw + 127) & ~(uintptr_t)127);

    const int b   = blockIdx.y;
    const int m0  = blockIdx.x * 128;
    const int tid = threadIdx.x;
    const int L1v = l1[b], L2v = l2[b];
    float* outTile = out + ((size_t)b * t1 + m0) * DD;

    if (m0 >= L1v || L2v == 0) {
        float4 z = make_float4(0.f, 0.f, 0.f, 0.f);
        for (int i = tid; i < 128 * DD / 4; i += NT) ((float4*)outTile)[i] = z;
        return;
    }

    const uint32_t smem = smem_u32(smc);
    const int lane = tid & 31;
    const int wid  = tid >> 5;

    const float* s1b = s1 + ((size_t)b * t1 + m0) * DD;
    const float4* w3v = (const float4*)(w + 2 * DD);

    const int bbase = b * 1024;
    const int krr = tid >> 3, khh = tid & 7;

    // issue chunk 0 into buffer 0
    {
        const char* srcH = g_s2hi + (size_t)(bbase + krr) * 512;
        const char* srcL = g_s2lo + (size_t)(bbase + krr) * 512;
        uint32_t dstH = smem + KBUF_OFF + (uint32_t)krr * 512;
        uint32_t dstL = dstH + 16384;
        #pragma unroll
        for (int p = 0; p < 4; p++) {
            int ch = khh + 8 * p;
            CP_ASYNC16(dstH + ch * 16, srcH + ch * 16);
            CP_ASYNC16(dstL + ch * 16, srcL + ch * 16);
        }
        if (tid < 8)
            CP_ASYNC16(smem + P2_OFF + tid * 16,
                       (const char*)(g_part2 + bbase) + tid * 16);
        CP_COMMIT();
    }

    // -------- prologue: Q = s1*w3 -> bf16 hi/lo smem (part1 cancels in softmax) ----
    {
        const int row = tid >> 1, h = tid & 1;
        const float4* qr = (const float4*)(s1b + row * DD);
        #pragma unroll
        for (int i = 0; i < 32; i++) {
            int c4 = 2 * i + h;
            float4 v = qr[c4];
            float4 m3 = w3v[c4];
            float q0 = v.x * m3.x, q1 = v.y * m3.y, q2 = v.z * m3.z, q3 = v.w * m3.w;
            uint32_t hA, lA, hB, lB;
            split2(q0, q1, hA, lA); split2(q2, q3, hB, lB);
            uint32_t off = swz(row, i, 512) + h * 8;
            *(uint2*)(smc + QHI_OFF + off) = make_uint2(hA, hB);
            *(uint2*)(smc + QLO_OFF + off) = make_uint2(lA, lB);
        }
    }
    __syncthreads();   // Q visible

    const int lam = lane & 3;
    const int r0l = wid * 16 + (lane >> 2);
    const int arow = wid * 16 + (lane & 15);
    const int brow = (lane & 7) + ((lane >> 4) & 1) * 8;

    float O[32][4];
    #pragma unroll
    for (int j = 0; j < 32; j++)
        #pragma unroll
        for (int e = 0; e < 4; e++) O[j][e] = 0.f;
    float mrow0 = -INFINITY, mrow1 = -INFINITY, lrow0 = 0.f, lrow1 = 0.f;

    const int nchunks = (L2v + 31) >> 5;
    for (int i = 0; i < nchunks; i++) {
        const int buf = i & 1;
        const uint32_t kh = smem + KBUF_OFF + (uint32_t)buf * KBUF_STRIDE;
        const uint32_t kl = kh + 16384;
        const float* p2f = (const float*)(smc + P2_OFF + buf * 128);
        const int c0 = i * 32;

        CP_WAIT0();          // chunk i landed
        __syncthreads();     // all warps done with buf^1's previous chunk

        // issue chunk i+1 into the other buffer
        if (i + 1 < nchunks) {
            const int cn = c0 + 32;
            const char* srcH = g_s2hi + (size_t)(bbase + cn + krr) * 512;
            const char* srcL = g_s2lo + (size_t)(bbase + cn + krr) * 512;
            uint32_t dstH = smem + KBUF_OFF + (uint32_t)(buf ^ 1) * KBUF_STRIDE
                            + (uint32_t)krr * 512;
            uint32_t dstL = dstH + 16384;
            #pragma unroll
            for (int p = 0; p < 4; p++) {
                int ch = khh + 8 * p;
                CP_ASYNC16(dstH + ch * 16, srcH + ch * 16);
                CP_ASYNC16(dstL + ch * 16, srcL + ch * 16);
            }
            if (tid < 8)
                CP_ASYNC16(smem + P2_OFF + (buf ^ 1) * 128 + tid * 16,
                           (const char*)(g_part2 + bbase + cn) + tid * 16);
            CP_COMMIT();
        }

        // ---- score: 16 rows x 32 cols, 3-term bf16 split ----
        float c[4][4];
        #pragma unroll
        for (int j = 0; j < 4; j++)
            #pragma unroll
            for (int e = 0; e < 4; e++) c[j][e] = 0.f;

        #pragma unroll 4
        for (int k = 0; k < 16; k++) {
            uint32_t aoff = swz(arow, 2 * k + (lane >> 4), 512);
            uint32_t ah0, ah1, ah2, ah3, al0, al1, al2, al3;
            ldsm_x4(ah0, ah1, ah2, ah3, smem + QHI_OFF + aoff);
            ldsm_x4(al0, al1, al2, al3, smem + QLO_OFF + aoff);
            #pragma unroll
            for (int nb = 0; nb < 2; nb++) {
                uint32_t boff = swz(brow + nb * 16, 2 * k + ((lane >> 3) & 1), 512);
                uint32_t bh0, bh1, bh2, bh3, bl0, bl1, bl2, bl3;
                ldsm_x4(bh0, bh1, bh2, bh3, kh + boff);
                ldsm_x4(bl0, bl1, bl2, bl3, kl + boff);
                mma16816(c[2 * nb], ah0, ah1, ah2, ah3, bh0, bh1);
                mma16816(c[2 * nb + 1], ah0, ah1, ah2, ah3, bh2, bh3);
                mma16816(c[2 * nb], ah0, ah1, ah2, ah3, bl0, bl1);
                mma16816(c[2 * nb + 1], ah0, ah1, ah2, ah3, bl2, bl3);
                mma16816(c[2 * nb], al0, al1, al2, al3, bh0, bh1);
                mma16816(c[2 * nb + 1], al0, al1, al2, al3, bh2, bh3);
            }
        }

        // ---- bias + mask + chunk max ----
        float mx0 = -INFINITY, mx1 = -INFINITY;
        #pragma unroll
        for (int j = 0; j < 4; j++) {
            #pragma unroll
            for (int e = 0; e < 2; e++) {
                int col = j * 8 + 2 * lam + e;
                bool valid = (c0 + col) < L2v;
                float bias = p2f[col];
                float s0 = c[j][e] + bias;
                float s1v = c[j][e + 2] + bias;
                s0 = valid ? s0 : NEG_BIG;
                s1v = valid ? s1v : NEG_BIG;
                c[j][e] = s0; c[j][e + 2] = s1v;
                mx0 = fmaxf(mx0, s0); mx1 = fmaxf(mx1, s1v);
            }
        }
        mx0 = fmaxf(mx0, __shfl_xor_sync(0xffffffffu, mx0, 1));
        mx0 = fmaxf(mx0, __shfl_xor_sync(0xffffffffu, mx0, 2));
        mx1 = fmaxf(mx1, __shfl_xor_sync(0xffffffffu, mx1, 1));
        mx1 = fmaxf(mx1, __shfl_xor_sync(0xffffffffu, mx1, 2));

        // ---- lazy rescale: only when a row sets a new record ----
        bool need = (mx0 > mrow0) || (mx1 > mrow1);
        if (__any_sync(0xffffffffu, need)) {
            const float mnew0 = (mx0 > mrow0) ? (mx0 + MHEAD) : mrow0;
            const float mnew1 = (mx1 > mrow1) ? (mx1 + MHEAD) : mrow1;
            const float alpha0 = __expf(mrow0 - mnew0);
            const float alpha1 = __expf(mrow1 - mnew1);
            mrow0 = mnew0; mrow1 = mnew1;
            lrow0 *= alpha0; lrow1 *= alpha1;
            #pragma unroll
            for (int j = 0; j < 32; j++) {
                O[j][0] *= alpha0; O[j][1] *= alpha0;
                O[j][2] *= alpha1; O[j][3] *= alpha1;
            }
        }

        // ---- exp + sums ----
        float sum0 = 0.f, sum1 = 0.f;
        #pragma unroll
        for (int j = 0; j < 4; j++) {
            c[j][0] = __expf(c[j][0] - mrow0);
            c[j][1] = __expf(c[j][1] - mrow0);
            c[j][2] = __expf(c[j][2] - mrow1);
            c[j][3] = __expf(c[j][3] - mrow1);
            sum0 += c[j][0] + c[j][1];
            sum1 += c[j][2] + c[j][3];
        }
        sum0 += __shfl_xor_sync(0xffffffffu, sum0, 1);
        sum0 += __shfl_xor_sync(0xffffffffu, sum0, 2);
        sum1 += __shfl_xor_sync(0xffffffffu, sum1, 1);
        sum1 += __shfl_xor_sync(0xffffffffu, sum1, 2);
        lrow0 += sum0;
        lrow1 += sum1;

        // ---- pack P c-frags into PV a-frags (in registers) ----
        uint32_t pah[8], pal[8];
        #pragma unroll
        for (int kk = 0; kk < 2; kk++) {
            const int J = 2 * kk;
            split2(c[J][0],     c[J][1],     pah[4 * kk + 0], pal[4 * kk + 0]);
            split2(c[J][2],     c[J][3],     pah[4 * kk + 1], pal[4 * kk + 1]);
            split2(c[J + 1][0], c[J + 1][1], pah[4 * kk + 2], pal[4 * kk + 2]);
            split2(c[J + 1][2], c[J + 1][3], pah[4 * kk + 3], pal[4 * kk + 3]);
        }

        // ---- PV: O += P(:, chunk) * V(chunk, :) ----
        #pragma unroll
        for (int kk = 0; kk < 2; kk++) {
            const int vrow = kk * 16 + (lane & 15);
            const uint32_t a0 = pah[4 * kk], a1 = pah[4 * kk + 1],
                           a2 = pah[4 * kk + 2], a3 = pah[4 * kk + 3];
            const uint32_t b0 = pal[4 * kk], b1 = pal[4 * kk + 1],
                           b2 = pal[4 * kk + 2], b3 = pal[4 * kk + 3];
            #pragma unroll
            for (int dblk = 0; dblk < 16; dblk++) {
                uint32_t boff = swz(vrow, 2 * dblk + (lane >> 4), 512);
                uint32_t vh0, vh1, vh2, vh3, vl0, vl1, vl2, vl3;
                ldsm_x4t(vh0, vh1, vh2, vh3, kh + boff);
                ldsm_x4t(vl0, vl1, vl2, vl3, kl + boff);
                mma16816(O[2 * dblk],     a0, a1, a2, a3, vh0, vh1);
                mma16816(O[2 * dblk + 1], a0, a1, a2, a3, vh2, vh3);
                mma16816(O[2 * dblk],     a0, a1, a2, a3, vl0, vl1);
                mma16816(O[2 * dblk + 1], a0, a1, a2, a3, vl2, vl3);
                mma16816(O[2 * dblk],     b0, b1, b2, b3, vh0, vh1);
                mma16816(O[2 * dblk + 1], b0, b1, b2, b3, vh2, vh3);
            }
        }
    }

    // ---------------- epilogue ----------------
    const int gr0 = m0 + r0l, gr1 = gr0 + 8;
    const float inv0 = (gr0 < L1v) ? (1.f / lrow0) : 0.f;
    const float inv1 = (gr1 < L1v) ? (1.f / lrow1) : 0.f;
    float* orow0 = outTile + r0l * DD + 2 * lam;
    float* orow1 = orow0 + 8 * DD;
    #pragma unroll
    for (int j = 0; j < 32; j++) {
        float2 v0; v0.x = O[j][0] * inv0; v0.y = O[j][1] * inv0;
        float2 v1; v1.x = O[j][2] * inv1; v1.y = O[j][3] * inv1;
        *(float2*)(orow0 + j * 8) = v0;
        *(float2*)(orow1 + j * 8) = v1;
    }
}

extern "C" void kernel_launch(void* const* d_in, const int* in_sizes, int n_in,
                              void* d_out, int out_size)
{
    const float* s1 = (const float*)d_in[0];
    const float* s2 = (const float*)d_in[1];
    const float* w  = (const float*)d_in[2];
    const int*   l1 = (const int*)d_in[3];
    const int*   l2 = (const int*)d_in[4];
    float* out = (float*)d_out;

    const int B  = in_sizes[3];
    const int D  = in_sizes[2] / 3;
    const int t1 = in_sizes[0] / (B * D);
    const int t2 = in_sizes[1] / (B * D);
    const int total_rows = B * t2;

    prep_s2<<<(total_rows + 31) / 32, 256>>>(s2, w, l2, t2, total_rows);

    cudaFuncSetAttribute(bidaf_fa2, cudaFuncAttributeMaxDynamicSharedMemorySize,
                         SMEM_BYTES);
    dim3 grid(t1 / 128, B);
    bidaf_fa2<<<grid, NT, SMEM_BYTES>>>(s1, s2, w, l1, l2, out, t1);
}

// round 16
// speedup vs baseline: 1.5917x; 1.0395x over previous
#include <cuda_runtime.h>
#include <cuda_bf16.h>
#include <cstdint>

#define NT 256
#define DD 256
#define NEG_BIG (-1e30f)
#define MHEAD 8.0f

// ---- static scratch: converted s2 (swizzle baked into 512B rows) + part2 ----
#define MAXROWS (32 * 1024)
__device__ __align__(128) char  g_s2hi[(size_t)MAXROWS * 512];
__device__ __align__(128) char  g_s2lo[(size_t)MAXROWS * 512];
__device__ __align__(128) float g_part2[MAXROWS];

// ---- smem byte offsets (from 128B-aligned base) ----
#define QHI_OFF 0           // [128][256] bf16 hi, 512B/row, swizzled
#define QLO_OFF 65536       // [128][256] bf16 lo
#define KBUF_OFF 131072     // 2 x { KHI 16KB, KLO 16KB }
#define KBUF_STRIDE 32768
#define P2_OFF  196608      // 2 x 128B bias slices
#define SMEM_USED 196864
#define SMEM_BYTES (SMEM_USED + 128)

__device__ __forceinline__ uint32_t smem_u32(const void* p) {
    uint32_t a;
    asm("{ .reg .u64 t; cvta.to.shared.u64 t, %1; cvt.u32.u64 %0, t; }"
        : "=r"(a) : "l"(p));
    return a;
}

#define CP_ASYNC16(dst, src) \
    asm volatile("cp.async.cg.shared.global [%0], [%1], 16;" \
        :: "r"(dst), "l"(src) : "memory")
#define CP_COMMIT() asm volatile("cp.async.commit_group;" ::: "memory")
#define CP_WAIT0()  asm volatile("cp.async.wait_group 0;" ::: "memory")

__device__ __forceinline__ void ldsm_x4(uint32_t& a0, uint32_t& a1, uint32_t& a2,
                                        uint32_t& a3, uint32_t addr) {
    asm volatile("ldmatrix.sync.aligned.m8n8.x4.shared.b16 {%0,%1,%2,%3}, [%4];"
                 : "=r"(a0), "=r"(a1), "=r"(a2), "=r"(a3) : "r"(addr));
}
__device__ __forceinline__ void ldsm_x4t(uint32_t& a0, uint32_t& a1, uint32_t& a2,
                                         uint32_t& a3, uint32_t addr) {
    asm volatile("ldmatrix.sync.aligned.m8n8.x4.trans.shared.b16 {%0,%1,%2,%3}, [%4];"
                 : "=r"(a0), "=r"(a1), "=r"(a2), "=r"(a3) : "r"(addr));
}
__device__ __forceinline__ void mma16816(float* c, uint32_t a0, uint32_t a1,
                                         uint32_t a2, uint32_t a3,
                                         uint32_t b0, uint32_t b1) {
    asm volatile(
        "mma.sync.aligned.m16n8k16.row.col.f32.bf16.bf16.f32 "
        "{%0,%1,%2,%3}, {%4,%5,%6,%7}, {%8,%9}, {%0,%1,%2,%3};"
        : "+f"(c[0]), "+f"(c[1]), "+f"(c[2]), "+f"(c[3])
        : "r"(a0), "r"(a1), "r"(a2), "r"(a3), "r"(b0), "r"(b1));
}

// swizzled chunk address: 16B chunks, XOR low-3 chunk bits with row&7
__device__ __forceinline__ uint32_t swz(int row, int chunk, int rowbytes) {
    int c = (chunk & ~7) | ((chunk & 7) ^ (row & 7));
    return (uint32_t)(row * rowbytes + c * 16);
}

__device__ __forceinline__ uint32_t pk2(__nv_bfloat16 a, __nv_bfloat16 b) {
    __nv_bfloat162 t; t.x = a; t.y = b;
    return *reinterpret_cast<uint32_t*>(&t);
}

__device__ __forceinline__ void split2(float a, float b, uint32_t& hi, uint32_t& lo) {
    __nv_bfloat16 ha = __float2bfloat16(a), hb = __float2bfloat16(b);
    float ra = a - __bfloat162float(ha), rb = b - __bfloat162float(hb);
    hi = pk2(ha, hb);
    lo = pk2(__float2bfloat16(ra), __float2bfloat16(rb));
}

// =============== prepass: s2 -> bf16 hi/lo (swizzled rows) + part2 ===============
// For masked rows (n >= l2[b]) only part2 = NEG_BIG is written: the main kernel
// then needs no per-element mask (exp(x + NEG_BIG - m) == 0 kills the column).
__global__ void __launch_bounds__(256, 2)
prep_s2(const float* __restrict__ s2, const float* __restrict__ w,
        const int* __restrict__ l2, int t2, int total_rows)
{
    const int row = blockIdx.x * 32 + (threadIdx.x >> 3);
    const int h   = threadIdx.x & 7;
    if (row >= total_rows) return;
    if ((row % t2) >= l2[row / t2]) {
        if (h == 0) g_part2[row] = NEG_BIG;
        return;
    }

    const float4* sr  = (const float4*)(s2 + (size_t)row * DD);
    const float4* w2v = (const float4*)(w + DD);
    char* hrow = g_s2hi + (size_t)row * 512;
    char* lrow = g_s2lo + (size_t)row * 512;

    float acc = 0.f;
    #pragma unroll
    for (int p = 0; p < 8; p++) {
        int c4 = h + 8 * p;
        float4 v = sr[c4];
        float4 a2 = w2v[c4];
        acc += v.x * a2.x + v.y * a2.y + v.z * a2.z + v.w * a2.w;
        uint32_t hA, lA, hB, lB;
        split2(v.x, v.y, hA, lA); split2(v.z, v.w, hB, lB);
        int chunk = c4 >> 1;
        uint32_t off = (uint32_t)(((chunk & ~7) | ((chunk & 7) ^ (row & 7))) * 16
                                  + (c4 & 1) * 8);
        *(uint2*)(hrow + off) = make_uint2(hA, hB);
        *(uint2*)(lrow + off) = make_uint2(lA, lB);
    }
    acc += __shfl_xor_sync(0xffffffffu, acc, 1);
    acc += __shfl_xor_sync(0xffffffffu, acc, 2);
    acc += __shfl_xor_sync(0xffffffffu, acc, 4);
    if (h == 0) g_part2[row] = acc;
}

// ============================== main kernel ==============================
__global__ void __launch_bounds__(NT, 1)
bidaf_fa2(const float* __restrict__ s1, const float* __restrict__ s2,
          const float* __restrict__ w, const int* __restrict__ l1,
          const int* __restrict__ l2, float* __restrict__ out, int t1)
{
    extern __shared__ char sm_raw[];
    char* smc = (char*)(((uintptr_t)sm_raw + 127) & ~(uintptr_t)127);

    const int b   = blockIdx.y;
    const int m0  = blockIdx.x * 128;
    const int tid = threadIdx.x;
    const int L1v = l1[b], L2v = l2[b];
    float* outTile = out + ((size_t)b * t1 + m0) * DD;

    if (m0 >= L1v || L2v == 0) {
        float4 z = make_float4(0.f, 0.f, 0.f, 0.f);
        for (int i = tid; i < 128 * DD / 4; i += NT) ((float4*)outTile)[i] = z;
        return;
    }

    const uint32_t smem = smem_u32(smc);
    const int lane = tid & 31;
    const int wid  = tid >> 5;

    const float* s1b = s1 + ((size_t)b * t1 + m0) * DD;
    const float4* w3v = (const float4*)(w + 2 * DD);

    const int bbase = b * 1024;
    const int krr = tid >> 3, khh = tid & 7;

    // issue chunk 0 into buffer 0
    {
        const char* srcH = g_s2hi + (size_t)(bbase + krr) * 512;
        const char* srcL = g_s2lo + (size_t)(bbase + krr) * 512;
        uint32_t dstH = smem + KBUF_OFF + (uint32_t)krr * 512;
        uint32_t dstL = dstH + 16384;
        #pragma unroll
        for (int p = 0; p < 4; p++) {
            int ch = khh + 8 * p;
            CP_ASYNC16(dstH + ch * 16, srcH + ch * 16);
            CP_ASYNC16(dstL + ch * 16, srcL + ch * 16);
        }
        if (tid < 8)
            CP_ASYNC16(smem + P2_OFF + tid * 16,
                       (const char*)(g_part2 + bbase) + tid * 16);
        CP_COMMIT();
    }

    // -------- prologue: Q = s1*w3 -> bf16 hi/lo smem (part1 cancels in softmax) ----
    {
        const int row = tid >> 1, h = tid & 1;
        const float4* qr = (const float4*)(s1b + row * DD);
        #pragma unroll
        for (int i = 0; i < 32; i++) {
            int c4 = 2 * i + h;
            float4 v = qr[c4];
            float4 m3 = w3v[c4];
            float q0 = v.x * m3.x, q1 = v.y * m3.y, q2 = v.z * m3.z, q3 = v.w * m3.w;
            uint32_t hA, lA, hB, lB;
            split2(q0, q1, hA, lA); split2(q2, q3, hB, lB);
            uint32_t off = swz(row, i, 512) + h * 8;
            *(uint2*)(smc + QHI_OFF + off) = make_uint2(hA, hB);
            *(uint2*)(smc + QLO_OFF + off) = make_uint2(lA, lB);
        }
    }
    __syncthreads();   // Q visible

    const int lam = lane & 3;
    const int r0l = wid * 16 + (lane >> 2);
    const int arow = wid * 16 + (lane & 15);
    const int brow = (lane & 7) + ((lane >> 4) & 1) * 8;

    float O[32][4];
    #pragma unroll
    for (int j = 0; j < 32; j++)
        #pragma unroll
        for (int e = 0; e < 4; e++) O[j][e] = 0.f;
    float mrow0 = -INFINITY, mrow1 = -INFINITY, lrow0 = 0.f, lrow1 = 0.f;

    const int nchunks = (L2v + 31) >> 5;
    for (int i = 0; i < nchunks; i++) {
        const int buf = i & 1;
        const uint32_t kh = smem + KBUF_OFF + (uint32_t)buf * KBUF_STRIDE;
        const uint32_t kl = kh + 16384;
        const float* p2f = (const float*)(smc + P2_OFF + buf * 128);
        const int c0 = i * 32;

        CP_WAIT0();          // chunk i landed
        __syncthreads();     // all warps done with buf^1's previous chunk

        // issue chunk i+1 into the other buffer
        if (i + 1 < nchunks) {
            const int cn = c0 + 32;
            const char* srcH = g_s2hi + (size_t)(bbase + cn + krr) * 512;
            const char* srcL = g_s2lo + (size_t)(bbase + cn + krr) * 512;
            uint32_t dstH = smem + KBUF_OFF + (uint32_t)(buf ^ 1) * KBUF_STRIDE
                            + (uint32_t)krr * 512;
            uint32_t dstL = dstH + 16384;
            #pragma unroll
            for (int p = 0; p < 4; p++) {
                int ch = khh + 8 * p;
                CP_ASYNC16(dstH + ch * 16, srcH + ch * 16);
                CP_ASYNC16(dstL + ch * 16, srcL + ch * 16);
            }
            if (tid < 8)
                CP_ASYNC16(smem + P2_OFF + (buf ^ 1) * 128 + tid * 16,
                           (const char*)(g_part2 + bbase + cn) + tid * 16);
            CP_COMMIT();
        }

        // ---- score: 16 rows x 32 cols, 3-term bf16 split (fully unrolled) ----
        float c[4][4];
        #pragma unroll
        for (int j = 0; j < 4; j++)
            #pragma unroll
            for (int e = 0; e < 4; e++) c[j][e] = 0.f;

        #pragma unroll
        for (int k = 0; k < 16; k++) {
            uint32_t aoff = swz(arow, 2 * k + (lane >> 4), 512);
            uint32_t ah0, ah1, ah2, ah3, al0, al1, al2, al3;
            ldsm_x4(ah0, ah1, ah2, ah3, smem + QHI_OFF + aoff);
            ldsm_x4(al0, al1, al2, al3, smem + QLO_OFF + aoff);
            #pragma unroll
            for (int nb = 0; nb < 2; nb++) {
                uint32_t boff = swz(brow + nb * 16, 2 * k + ((lane >> 3) & 1), 512);
                uint32_t bh0, bh1, bh2, bh3, bl0, bl1, bl2, bl3;
                ldsm_x4(bh0, bh1, bh2, bh3, kh + boff);
                ldsm_x4(bl0, bl1, bl2, bl3, kl + boff);
                mma16816(c[2 * nb], ah0, ah1, ah2, ah3, bh0, bh1);
                mma16816(c[2 * nb + 1], ah0, ah1, ah2, ah3, bh2, bh3);
                mma16816(c[2 * nb], ah0, ah1, ah2, ah3, bl0, bl1);
                mma16816(c[2 * nb + 1], ah0, ah1, ah2, ah3, bl2, bl3);
                mma16816(c[2 * nb], al0, al1, al2, al3, bh0, bh1);
                mma16816(c[2 * nb + 1], al0, al1, al2, al3, bh2, bh3);
            }
        }

        // ---- bias (mask baked into bias) + chunk max ----
        float mx0 = -INFINITY, mx1 = -INFINITY;
        #pragma unroll
        for (int j = 0; j < 4; j++) {
            #pragma unroll
            for (int e = 0; e < 2; e++) {
                int col = j * 8 + 2 * lam + e;
                float bias = p2f[col];
                float s0 = c[j][e] + bias;
                float s1v = c[j][e + 2] + bias;
                c[j][e] = s0; c[j][e + 2] = s1v;
                mx0 = fmaxf(mx0, s0); mx1 = fmaxf(mx1, s1v);
            }
        }
        mx0 = fmaxf(mx0, __shfl_xor_sync(0xffffffffu, mx0, 1));
        mx0 = fmaxf(mx0, __shfl_xor_sync(0xffffffffu, mx0, 2));
        mx1 = fmaxf(mx1, __shfl_xor_sync(0xffffffffu, mx1, 1));
        mx1 = fmaxf(mx1, __shfl_xor_sync(0xffffffffu, mx1, 2));

        // ---- lazy rescale: only when a row sets a new record ----
        bool need = (mx0 > mrow0) || (mx1 > mrow1);
        if (__any_sync(0xffffffffu, need)) {
            const float mnew0 = (mx0 > mrow0) ? (mx0 + MHEAD) : mrow0;
            const float mnew1 = (mx1 > mrow1) ? (mx1 + MHEAD) : mrow1;
            const float alpha0 = __expf(mrow0 - mnew0);
            const float alpha1 = __expf(mrow1 - mnew1);
            mrow0 = mnew0; mrow1 = mnew1;
            lrow0 *= alpha0; lrow1 *= alpha1;
            #pragma unroll
            for (int j = 0; j < 32; j++) {
                O[j][0] *= alpha0; O[j][1] *= alpha0;
                O[j][2] *= alpha1; O[j][3] *= alpha1;
            }
        }

        // ---- exp + sums ----
        float sum0 = 0.f, sum1 = 0.f;
        #pragma unroll
        for (int j = 0; j < 4; j++) {
            c[j][0] = __expf(c[j][0] - mrow0);
            c[j][1] = __expf(c[j][1] - mrow0);
            c[j][2] = __expf(c[j][2] - mrow1);
            c[j][3] = __expf(c[j][3] - mrow1);
            sum0 += c[j][0] + c[j][1];
            sum1 += c[j][2] + c[j][3];
        }
        sum0 += __shfl_xor_sync(0xffffffffu, sum0, 1);
        sum0 += __shfl_xor_sync(0xffffffffu, sum0, 2);
        sum1 += __shfl_xor_sync(0xffffffffu, sum1, 1);
        sum1 += __shfl_xor_sync(0xffffffffu, sum1, 2);
        lrow0 += sum0;
        lrow1 += sum1;

        // ---- pack P c-frags into PV a-frags (bf16 hi + residual lo) ----
        uint32_t pah[8], pal[8];
        #pragma unroll
        for (int kk = 0; kk < 2; kk++) {
            const int J = 2 * kk;
            split2(c[J][0],     c[J][1],     pah[4 * kk + 0], pal[4 * kk + 0]);
            split2(c[J][2],     c[J][3],     pah[4 * kk + 1], pal[4 * kk + 1]);
            split2(c[J + 1][0], c[J + 1][1], pah[4 * kk + 2], pal[4 * kk + 2]);
            split2(c[J + 1][2], c[J + 1][3], pah[4 * kk + 3], pal[4 * kk + 3]);
        }

        // ---- PV: O += Phi*(Vhi+Vlo) + Plo*Vhi ----
        #pragma unroll
        for (int kk = 0; kk < 2; kk++) {
            const int vrow = kk * 16 + (lane & 15);
            const uint32_t a0 = pah[4 * kk], a1 = pah[4 * kk + 1],
                           a2 = pah[4 * kk + 2], a3 = pah[4 * kk + 3];
            const uint32_t b0 = pal[4 * kk], b1 = pal[4 * kk + 1],
                           b2 = pal[4 * kk + 2], b3 = pal[4 * kk + 3];
            #pragma unroll
            for (int dblk = 0; dblk < 16; dblk++) {
                uint32_t boff = swz(vrow, 2 * dblk + (lane >> 4), 512);
                uint32_t vh0, vh1, vh2, vh3, vl0, vl1, vl2, vl3;
                ldsm_x4t(vh0, vh1, vh2, vh3, kh + boff);
                ldsm_x4t(vl0, vl1, vl2, vl3, kl + boff);
                mma16816(O[2 * dblk],     a0, a1, a2, a3, vh0, vh1);
                mma16816(O[2 * dblk + 1], a0, a1, a2, a3, vh2, vh3);
                mma16816(O[2 * dblk],     a0, a1, a2, a3, vl0, vl1);
                mma16816(O[2 * dblk + 1], a0, a1, a2, a3, vl2, vl3);
                mma16816(O[2 * dblk],     b0, b1, b2, b3, vh0, vh1);
                mma16816(O[2 * dblk + 1], b0, b1, b2, b3, vh2, vh3);
            }
        }
    }

    // ---------------- epilogue ----------------
    const int gr0 = m0 + r0l, gr1 = gr0 + 8;
    const float inv0 = (gr0 < L1v) ? (1.f / lrow0) : 0.f;
    const float inv1 = (gr1 < L1v) ? (1.f / lrow1) : 0.f;
    float* orow0 = outTile + r0l * DD + 2 * lam;
    float* orow1 = orow0 + 8 * DD;
    #pragma unroll
    for (int j = 0; j < 32; j++) {
        float2 v0; v0.x = O[j][0] * inv0; v0.y = O[j][1] * inv0;
        float2 v1; v1.x = O[j][2] * inv1; v1.y = O[j][3] * inv1;
        *(float2*)(orow0 + j * 8) = v0;
        *(float2*)(orow1 + j * 8) = v1;
    }
}

extern "C" void kernel_launch(void* const* d_in, const int* in_sizes, int n_in,
                              void* d_out, int out_size)
{
    const float* s1 = (const float*)d_in[0];
    const float* s2 = (const float*)d_in[1];
    const float* w  = (const float*)d_in[2];
    const int*   l1 = (const int*)d_in[3];
    const int*   l2 = (const int*)d_in[4];
    float* out = (float*)d_out;

    const int B  = in_sizes[3];
    const int D  = in_sizes[2] / 3;
    const int t1 = in_sizes[0] / (B * D);
    const int t2 = in_sizes[1] / (B * D);
    const int total_rows = B * t2;

    prep_s2<<<(total_rows + 31) / 32, 256>>>(s2, w, l2, t2, total_rows);

    cudaFuncSetAttribute(bidaf_fa2, cudaFuncAttributeMaxDynamicSharedMemorySize,
                         SMEM_BYTES);
    dim3 grid(t1 / 128, B);
    bidaf_fa2<<<grid, NT, SMEM_BYTES>>>(s1, s2, w, l1, l2, out, t1);
}

// round 17
// speedup vs baseline: 1.8546x; 1.1652x over previous
#include <cuda_runtime.h>
#include <cuda_bf16.h>
#include <cstdint>

#define NT 256
#define DD 256
#define NEG_BIG (-1e30f)
#define MHEAD 8.0f

// ---- static scratch: converted s2 (swizzle baked into 512B rows) + part2 ----
#define MAXROWS (32 * 1024)
__device__ __align__(128) char  g_s2hi[(size_t)MAXROWS * 512];
__device__ __align__(128) char  g_s2lo[(size_t)MAXROWS * 512];
__device__ __align__(128) float g_part2[MAXROWS];

// ---- smem byte offsets (from 128B-aligned base) ----
#define QHI_OFF 0           // [128][256] bf16 hi, 512B/row, swizzled
#define QLO_OFF 65536       // [128][256] bf16 lo
#define KBUF_OFF 131072     // 2 x { KHI 16KB, KLO 16KB }
#define KBUF_STRIDE 32768
#define P2_OFF  196608      // 2 x 128B bias slices
#define SMEM_USED 196864
#define SMEM_BYTES (SMEM_USED + 128)

__device__ __forceinline__ uint32_t smem_u32(const void* p) {
    uint32_t a;
    asm("{ .reg .u64 t; cvta.to.shared.u64 t, %1; cvt.u32.u64 %0, t; }"
        : "=r"(a) : "l"(p));
    return a;
}

#define CP_ASYNC16(dst, src) \
    asm volatile("cp.async.cg.shared.global [%0], [%1], 16;" \
        :: "r"(dst), "l"(src) : "memory")
#define CP_COMMIT() asm volatile("cp.async.commit_group;" ::: "memory")
#define CP_WAIT0()  asm volatile("cp.async.wait_group 0;" ::: "memory")

__device__ __forceinline__ void ldsm_x4(uint32_t& a0, uint32_t& a1, uint32_t& a2,
                                        uint32_t& a3, uint32_t addr) {
    asm volatile("ldmatrix.sync.aligned.m8n8.x4.shared.b16 {%0,%1,%2,%3}, [%4];"
                 : "=r"(a0), "=r"(a1), "=r"(a2), "=r"(a3) : "r"(addr));
}
__device__ __forceinline__ void ldsm_x4t(uint32_t& a0, uint32_t& a1, uint32_t& a2,
                                         uint32_t& a3, uint32_t addr) {
    asm volatile("ldmatrix.sync.aligned.m8n8.x4.trans.shared.b16 {%0,%1,%2,%3}, [%4];"
                 : "=r"(a0), "=r"(a1), "=r"(a2), "=r"(a3) : "r"(addr));
}
__device__ __forceinline__ void mma16816(float* c, uint32_t a0, uint32_t a1,
                                         uint32_t a2, uint32_t a3,
                                         uint32_t b0, uint32_t b1) {
    asm volatile(
        "mma.sync.aligned.m16n8k16.row.col.f32.bf16.bf16.f32 "
        "{%0,%1,%2,%3}, {%4,%5,%6,%7}, {%8,%9}, {%0,%1,%2,%3};"
        : "+f"(c[0]), "+f"(c[1]), "+f"(c[2]), "+f"(c[3])
        : "r"(a0), "r"(a1), "r"(a2), "r"(a3), "r"(b0), "r"(b1));
}

// swizzled chunk address: 16B chunks, XOR low-3 chunk bits with row&7
__device__ __forceinline__ uint32_t swz(int row, int chunk, int rowbytes) {
    int c = (chunk & ~7) | ((chunk & 7) ^ (row & 7));
    return (uint32_t)(row * rowbytes + c * 16);
}

__device__ __forceinline__ uint32_t pk2(__nv_bfloat16 a, __nv_bfloat16 b) {
    __nv_bfloat162 t; t.x = a; t.y = b;
    return *reinterpret_cast<uint32_t*>(&t);
}

__device__ __forceinline__ void split2(float a, float b, uint32_t& hi, uint32_t& lo) {
    __nv_bfloat16 ha = __float2bfloat16(a), hb = __float2bfloat16(b);
    float ra = a - __bfloat162float(ha), rb = b - __bfloat162float(hb);
    hi = pk2(ha, hb);
    lo = pk2(__float2bfloat16(ra), __float2bfloat16(rb));
}

// =============== prepass: s2 -> bf16 hi/lo (swizzled rows) + part2 ===============
// For masked rows (n >= l2[b]) only part2 = NEG_BIG is written: the main kernel
// then needs no per-element mask (exp(x + NEG_BIG - m) == 0 kills the column).
__global__ void __launch_bounds__(256, 2)
prep_s2(const float* __restrict__ s2, const float* __restrict__ w,
        const int* __restrict__ l2, int t2, int total_rows)
{
    const int row = blockIdx.x * 32 + (threadIdx.x >> 3);
    const int h   = threadIdx.x & 7;
    if (row >= total_rows) return;
    if ((row % t2) >= l2[row / t2]) {
        if (h == 0) g_part2[row] = NEG_BIG;
        return;
    }

    const float4* sr  = (const float4*)(s2 + (size_t)row * DD);
    const float4* w2v = (const float4*)(w + DD);
    char* hrow = g_s2hi + (size_t)row * 512;
    char* lrow = g_s2lo + (size_t)row * 512;

    float acc = 0.f;
    #pragma unroll
    for (int p = 0; p < 8; p++) {
        int c4 = h + 8 * p;
        float4 v = sr[c4];
        float4 a2 = w2v[c4];
        acc += v.x * a2.x + v.y * a2.y + v.z * a2.z + v.w * a2.w;
        uint32_t hA, lA, hB, lB;
        split2(v.x, v.y, hA, lA); split2(v.z, v.w, hB, lB);
        int chunk = c4 >> 1;
        uint32_t off = (uint32_t)(((chunk & ~7) | ((chunk & 7) ^ (row & 7))) * 16
                                  + (c4 & 1) * 8);
        *(uint2*)(hrow + off) = make_uint2(hA, hB);
        *(uint2*)(lrow + off) = make_uint2(lA, lB);
    }
    acc += __shfl_xor_sync(0xffffffffu, acc, 1);
    acc += __shfl_xor_sync(0xffffffffu, acc, 2);
    acc += __shfl_xor_sync(0xffffffffu, acc, 4);
    if (h == 0) g_part2[row] = acc;
}

// ============================== main kernel ==============================
__global__ void __launch_bounds__(NT, 1)
bidaf_fa2(const float* __restrict__ s1, const float* __restrict__ s2,
          const float* __restrict__ w, const int* __restrict__ l1,
          const int* __restrict__ l2, float* __restrict__ out, int t1)
{
    extern __shared__ char sm_raw[];
    char* smc = (char*)(((uintptr_t)sm_raw + 127) & ~(uintptr_t)127);

    const int b   = blockIdx.y;
    const int m0  = blockIdx.x * 128;
    const int tid = threadIdx.x;
    const int L1v = l1[b], L2v = l2[b];
    float* outTile = out + ((size_t)b * t1 + m0) * DD;

    if (m0 >= L1v || L2v == 0) {
        float4 z = make_float4(0.f, 0.f, 0.f, 0.f);
        for (int i = tid; i < 128 * DD / 4; i += NT) ((float4*)outTile)[i] = z;
        return;
    }

    const uint32_t smem = smem_u32(smc);
    const int lane = tid & 31;
    const int wid  = tid >> 5;

    const float* s1b = s1 + ((size_t)b * t1 + m0) * DD;
    const float4* w3v = (const float4*)(w + 2 * DD);

    const int bbase = b * 1024;
    const int krr = tid >> 3, khh = tid & 7;

    // issue chunk 0 into buffer 0
    {
        const char* srcH = g_s2hi + (size_t)(bbase + krr) * 512;
        const char* srcL = g_s2lo + (size_t)(bbase + krr) * 512;
        uint32_t dstH = smem + KBUF_OFF + (uint32_t)krr * 512;
        uint32_t dstL = dstH + 16384;
        #pragma unroll
        for (int p = 0; p < 4; p++) {
            int ch = khh + 8 * p;
            CP_ASYNC16(dstH + ch * 16, srcH + ch * 16);
            CP_ASYNC16(dstL + ch * 16, srcL + ch * 16);
        }
        if (tid < 8)
            CP_ASYNC16(smem + P2_OFF + tid * 16,
                       (const char*)(g_part2 + bbase) + tid * 16);
        CP_COMMIT();
    }

    // -------- prologue: Q = s1*w3 -> bf16 hi/lo smem (part1 cancels in softmax) ----
    {
        const int row = tid >> 1, h = tid & 1;
        const float4* qr = (const float4*)(s1b + row * DD);
        #pragma unroll
        for (int i = 0; i < 32; i++) {
            int c4 = 2 * i + h;
            float4 v = qr[c4];
            float4 m3 = w3v[c4];
            float q0 = v.x * m3.x, q1 = v.y * m3.y, q2 = v.z * m3.z, q3 = v.w * m3.w;
            uint32_t hA, lA, hB, lB;
            split2(q0, q1, hA, lA); split2(q2, q3, hB, lB);
            uint32_t off = swz(row, i, 512) + h * 8;
            *(uint2*)(smc + QHI_OFF + off) = make_uint2(hA, hB);
            *(uint2*)(smc + QLO_OFF + off) = make_uint2(lA, lB);
        }
    }
    __syncthreads();   // Q visible

    const int lam = lane & 3;
    const int r0l = wid * 16 + (lane >> 2);
    const int arow = wid * 16 + (lane & 15);
    const int brow = (lane & 7) + ((lane >> 4) & 1) * 8;

    float O[32][4];
    #pragma unroll
    for (int j = 0; j < 32; j++)
        #pragma unroll
        for (int e = 0; e < 4; e++) O[j][e] = 0.f;
    float mrow0 = -INFINITY, mrow1 = -INFINITY, lrow0 = 0.f, lrow1 = 0.f;

    const int nchunks = (L2v + 31) >> 5;
    for (int i = 0; i < nchunks; i++) {
        const int buf = i & 1;
        const uint32_t kh = smem + KBUF_OFF + (uint32_t)buf * KBUF_STRIDE;
        const uint32_t kl = kh + 16384;
        const float* p2f = (const float*)(smc + P2_OFF + buf * 128);
        const int c0 = i * 32;

        CP_WAIT0();          // chunk i landed
        __syncthreads();     // all warps done with buf^1's previous chunk

        // issue chunk i+1 into the other buffer
        if (i + 1 < nchunks) {
            const int cn = c0 + 32;
            const char* srcH = g_s2hi + (size_t)(bbase + cn + krr) * 512;
            const char* srcL = g_s2lo + (size_t)(bbase + cn + krr) * 512;
            uint32_t dstH = smem + KBUF_OFF + (uint32_t)(buf ^ 1) * KBUF_STRIDE
                            + (uint32_t)krr * 512;
            uint32_t dstL = dstH + 16384;
            #pragma unroll
            for (int p = 0; p < 4; p++) {
                int ch = khh + 8 * p;
                CP_ASYNC16(dstH + ch * 16, srcH + ch * 16);
                CP_ASYNC16(dstL + ch * 16, srcL + ch * 16);
            }
            if (tid < 8)
                CP_ASYNC16(smem + P2_OFF + (buf ^ 1) * 128 + tid * 16,
                           (const char*)(g_part2 + bbase + cn) + tid * 16);
            CP_COMMIT();
        }

        // ---- score: 16 rows x 32 cols, 3-term bf16 split (fully unrolled) ----
        float c[4][4];
        #pragma unroll
        for (int j = 0; j < 4; j++)
            #pragma unroll
            for (int e = 0; e < 4; e++) c[j][e] = 0.f;

        #pragma unroll
        for (int k = 0; k < 16; k++) {
            uint32_t aoff = swz(arow, 2 * k + (lane >> 4), 512);
            uint32_t ah0, ah1, ah2, ah3, al0, al1, al2, al3;
            ldsm_x4(ah0, ah1, ah2, ah3, smem + QHI_OFF + aoff);
            ldsm_x4(al0, al1, al2, al3, smem + QLO_OFF + aoff);
            #pragma unroll
            for (int nb = 0; nb < 2; nb++) {
                uint32_t boff = swz(brow + nb * 16, 2 * k + ((lane >> 3) & 1), 512);
                uint32_t bh0, bh1, bh2, bh3, bl0, bl1, bl2, bl3;
                ldsm_x4(bh0, bh1, bh2, bh3, kh + boff);
                ldsm_x4(bl0, bl1, bl2, bl3, kl + boff);
                mma16816(c[2 * nb], ah0, ah1, ah2, ah3, bh0, bh1);
                mma16816(c[2 * nb + 1], ah0, ah1, ah2, ah3, bh2, bh3);
                mma16816(c[2 * nb], ah0, ah1, ah2, ah3, bl0, bl1);
                mma16816(c[2 * nb + 1], ah0, ah1, ah2, ah3, bl2, bl3);
                mma16816(c[2 * nb], al0, al1, al2, al3, bh0, bh1);
                mma16816(c[2 * nb + 1], al0, al1, al2, al3, bh2, bh3);
            }
        }

        // ---- bias (mask baked into bias) + chunk max ----
        float mx0 = -INFINITY, mx1 = -INFINITY;
        #pragma unroll
        for (int j = 0; j < 4; j++) {
            #pragma unroll
            for (int e = 0; e < 2; e++) {
                int col = j * 8 + 2 * lam + e;
                float bias = p2f[col];
                float s0 = c[j][e] + bias;
                float s1v = c[j][e + 2] + bias;
                c[j][e] = s0; c[j][e + 2] = s1v;
                mx0 = fmaxf(mx0, s0); mx1 = fmaxf(mx1, s1v);
            }
        }
        mx0 = fmaxf(mx0, __shfl_xor_sync(0xffffffffu, mx0, 1));
        mx0 = fmaxf(mx0, __shfl_xor_sync(0xffffffffu, mx0, 2));
        mx1 = fmaxf(mx1, __shfl_xor_sync(0xffffffffu, mx1, 1));
        mx1 = fmaxf(mx1, __shfl_xor_sync(0xffffffffu, mx1, 2));

        // ---- lazy rescale: only when a row sets a new record ----
        bool need = (mx0 > mrow0) || (mx1 > mrow1);
        if (__any_sync(0xffffffffu, need)) {
            const float mnew0 = (mx0 > mrow0) ? (mx0 + MHEAD) : mrow0;
            const float mnew1 = (mx1 > mrow1) ? (mx1 + MHEAD) : mrow1;
            const float alpha0 = __expf(mrow0 - mnew0);
            const float alpha1 = __expf(mrow1 - mnew1);
            mrow0 = mnew0; mrow1 = mnew1;
            lrow0 *= alpha0; lrow1 *= alpha1;
            #pragma unroll
            for (int j = 0; j < 32; j++) {
                O[j][0] *= alpha0; O[j][1] *= alpha0;
                O[j][2] *= alpha1; O[j][3] *= alpha1;
            }
        }

        // ---- exp + bf16 round; accumulate l from the ROUNDED p so the
        //      numerator (PV in bf16) and denominator stay consistent ----
        uint32_t pah[8];
        float sum0 = 0.f, sum1 = 0.f;
        #pragma unroll
        for (int kk = 0; kk < 2; kk++) {
            const int J = 2 * kk;
            #pragma unroll
            for (int jj = 0; jj < 2; jj++) {
                const int j = J + jj;
                __nv_bfloat16 p0 = __float2bfloat16(__expf(c[j][0] - mrow0));
                __nv_bfloat16 p1 = __float2bfloat16(__expf(c[j][1] - mrow0));
                __nv_bfloat16 p2 = __float2bfloat16(__expf(c[j][2] - mrow1));
                __nv_bfloat16 p3 = __float2bfloat16(__expf(c[j][3] - mrow1));
                sum0 += __bfloat162float(p0) + __bfloat162float(p1);
                sum1 += __bfloat162float(p2) + __bfloat162float(p3);
                pah[4 * kk + 2 * jj]     = pk2(p0, p1);
                pah[4 * kk + 2 * jj + 1] = pk2(p2, p3);
            }
        }
        sum0 += __shfl_xor_sync(0xffffffffu, sum0, 1);
        sum0 += __shfl_xor_sync(0xffffffffu, sum0, 2);
        sum1 += __shfl_xor_sync(0xffffffffu, sum1, 1);
        sum1 += __shfl_xor_sync(0xffffffffu, sum1, 2);
        lrow0 += sum0;
        lrow1 += sum1;

        // ---- PV: O += Phat * (Vhi + Vlo) ----
        #pragma unroll
        for (int kk = 0; kk < 2; kk++) {
            const int vrow = kk * 16 + (lane & 15);
            const uint32_t a0 = pah[4 * kk], a1 = pah[4 * kk + 1],
                           a2 = pah[4 * kk + 2], a3 = pah[4 * kk + 3];
            #pragma unroll
            for (int dblk = 0; dblk < 16; dblk++) {
                uint32_t boff = swz(vrow, 2 * dblk + (lane >> 4), 512);
                uint32_t vh0, vh1, vh2, vh3, vl0, vl1, vl2, vl3;
                ldsm_x4t(vh0, vh1, vh2, vh3, kh + boff);
                ldsm_x4t(vl0, vl1, vl2, vl3, kl + boff);
                mma16816(O[2 * dblk],     a0, a1, a2, a3, vh0, vh1);
                mma16816(O[2 * dblk + 1], a0, a1, a2, a3, vh2, vh3);
                mma16816(O[2 * dblk],     a0, a1, a2, a3, vl0, vl1);
                mma16816(O[2 * dblk + 1], a0, a1, a2, a3, vl2, vl3);
            }
        }
    }

    // ---------------- epilogue ----------------
    const int gr0 = m0 + r0l, gr1 = gr0 + 8;
    const float inv0 = (gr0 < L1v) ? (1.f / lrow0) : 0.f;
    const float inv1 = (gr1 < L1v) ? (1.f / lrow1) : 0.f;
    float* orow0 = outTile + r0l * DD + 2 * lam;
    float* orow1 = orow0 + 8 * DD;
    #pragma unroll
    for (int j = 0; j < 32; j++) {
        float2 v0; v0.x = O[j][0] * inv0; v0.y = O[j][1] * inv0;
        float2 v1; v1.x = O[j][2] * inv1; v1.y = O[j][3] * inv1;
        *(float2*)(orow0 + j * 8) = v0;
        *(float2*)(orow1 + j * 8) = v1;
    }
}

extern "C" void kernel_launch(void* const* d_in, const int* in_sizes, int n_in,
                              void* d_out, int out_size)
{
    const float* s1 = (const float*)d_in[0];
    const float* s2 = (const float*)d_in[1];
    const float* w  = (const float*)d_in[2];
    const int*   l1 = (const int*)d_in[3];
    const int*   l2 = (const int*)d_in[4];
    float* out = (float*)d_out;

    const int B  = in_sizes[3];
    const int D  = in_sizes[2] / 3;
    const int t1 = in_sizes[0] / (B * D);
    const int t2 = in_sizes[1] / (B * D);
    const int total_rows = B * t2;

    prep_s2<<<(total_rows + 31) / 32, 256>>>(s2, w, l2, t2, total_rows);

    cudaFuncSetAttribute(bidaf_fa2, cudaFuncAttributeMaxDynamicSharedMemorySize,
                         SMEM_BYTES);
    dim3 grid(t1 / 128, B);
    bidaf_fa2<<<grid, NT, SMEM_BYTES>>>(s1, s2, w, l1, l2, out, t1);
}